// round 2
// baseline (speedup 1.0000x reference)
#include <cuda_runtime.h>
#include <math.h>

#define HID   1024
#define BATCH 32
#define SEQ   512
#define RIMG  196
#define BM 128
#define BN 128
#define BK 8
#define NCT (HID / BN)   // 8 column tiles

// Scratch (device globals; no allocation allowed)
__device__ float g_part1[NCT * BATCH * RIMG];   // per-coltile partial scores (img path)
__device__ float g_part2[NCT * BATCH * SEQ];    // per-coltile partial scores (dns path)
__device__ float g_w1[BATCH * RIMG];            // visual softmax weights
__device__ float g_w2[BATCH * SEQ];             // textual softmax weights
__device__ float g_v[BATCH * HID];              // att_img row per batch
__device__ float g_u[BATCH * HID];              // att_dns row per batch

// ---------------------------------------------------------------------------
// Fused GEMM (C = X · Wᵀ) + tanh + dot-with-wvec, reduced over the 128-col
// tile to one partial scalar per row. part[coltile][row] layout (deterministic,
// no atomics).
// ---------------------------------------------------------------------------
__global__ __launch_bounds__(256, 2)
void gemm_tanh_dot(const float* __restrict__ X, const float* __restrict__ W,
                   const float* __restrict__ wvec, float* __restrict__ part, int N)
{
    __shared__ __align__(16) float As[BK][BM + 4];
    __shared__ __align__(16) float Bs[BK][BN + 4];
    __shared__ float red[16][BM + 1];

    const int tid  = threadIdx.x;
    const int tx   = tid & 15;
    const int ty   = tid >> 4;
    const int row0 = blockIdx.x * BM;
    const int col0 = blockIdx.y * BN;

    const int lrow = tid >> 1;
    const int lseg = (tid & 1) * 4;

    const float* Ap = X + (size_t)(row0 + lrow) * HID + lseg;
    const float* Bp = W + (size_t)(col0 + lrow) * HID + lseg;

    float acc[8][8];
#pragma unroll
    for (int i = 0; i < 8; i++)
#pragma unroll
        for (int j = 0; j < 8; j++) acc[i][j] = 0.f;

    for (int k0 = 0; k0 < HID; k0 += BK) {
        float4 a4 = *(const float4*)(Ap + k0);
        float4 b4 = *(const float4*)(Bp + k0);
        __syncthreads();
        As[lseg + 0][lrow] = a4.x;
        As[lseg + 1][lrow] = a4.y;
        As[lseg + 2][lrow] = a4.z;
        As[lseg + 3][lrow] = a4.w;
        Bs[lseg + 0][lrow] = b4.x;
        Bs[lseg + 1][lrow] = b4.y;
        Bs[lseg + 2][lrow] = b4.z;
        Bs[lseg + 3][lrow] = b4.w;
        __syncthreads();
#pragma unroll
        for (int k = 0; k < BK; k++) {
            float4 a0 = *(const float4*)&As[k][ty * 8];
            float4 a1 = *(const float4*)&As[k][ty * 8 + 4];
            float4 b0 = *(const float4*)&Bs[k][tx * 8];
            float4 b1 = *(const float4*)&Bs[k][tx * 8 + 4];
            float a[8] = {a0.x, a0.y, a0.z, a0.w, a1.x, a1.y, a1.z, a1.w};
            float b[8] = {b0.x, b0.y, b0.z, b0.w, b1.x, b1.y, b1.z, b1.w};
#pragma unroll
            for (int i = 0; i < 8; i++)
#pragma unroll
                for (int j = 0; j < 8; j++)
                    acc[i][j] = fmaf(a[i], b[j], acc[i][j]);
        }
    }

    float wv[8];
#pragma unroll
    for (int j = 0; j < 8; j++) wv[j] = wvec[col0 + tx * 8 + j];

#pragma unroll
    for (int i = 0; i < 8; i++) {
        float p = 0.f;
#pragma unroll
        for (int j = 0; j < 8; j++) p = fmaf(tanhf(acc[i][j]), wv[j], p);
        red[tx][ty * 8 + i] = p;
    }
    __syncthreads();
    if (tid < BM) {
        float s = 0.f;
#pragma unroll
        for (int t = 0; t < 16; t++) s += red[t][tid];
        part[blockIdx.y * N + row0 + tid] = s;
    }
}

// ---------------------------------------------------------------------------
// Softmax over n logits per batch row; logits come in as NCT partials.
// ---------------------------------------------------------------------------
__device__ __forceinline__ float warpRedMax(float v) {
#pragma unroll
    for (int o = 16; o > 0; o >>= 1) v = fmaxf(v, __shfl_xor_sync(0xffffffffu, v, o));
    return v;
}
__device__ __forceinline__ float warpRedSum(float v) {
#pragma unroll
    for (int o = 16; o > 0; o >>= 1) v += __shfl_xor_sync(0xffffffffu, v, o);
    return v;
}

__global__ void softmax_rows(const float* __restrict__ part, int N, int n,
                             float* __restrict__ w)
{
    __shared__ float sh[8];
    const int b    = blockIdx.x;
    const int tid  = threadIdx.x;   // 256
    const int base = b * n;

    float m = -1e30f;
    for (int i = tid; i < n; i += 256) {
        float x = 0.f;
#pragma unroll
        for (int c = 0; c < NCT; c++) x += part[c * N + base + i];
        w[base + i] = x;
        m = fmaxf(m, x);
    }
    m = warpRedMax(m);
    if ((tid & 31) == 0) sh[tid >> 5] = m;
    __syncthreads();
    float M = sh[0];
#pragma unroll
    for (int t = 1; t < 8; t++) M = fmaxf(M, sh[t]);

    float sum = 0.f;
    for (int i = tid; i < n; i += 256) {
        float e = expf(w[base + i] - M);
        w[base + i] = e;
        sum += e;
    }
    sum = warpRedSum(sum);
    __syncthreads();
    if ((tid & 31) == 0) sh[tid >> 5] = sum;
    __syncthreads();
    float S = 0.f;
#pragma unroll
    for (int t = 0; t < 8; t++) S += sh[t];
    const float inv = 1.f / S;
    for (int i = tid; i < n; i += 256) w[base + i] *= inv;
}

// ---------------------------------------------------------------------------
// out[b, h] = sum_r w[b,r] * X[b, r, h]
// ---------------------------------------------------------------------------
__global__ void wsum_kernel(const float* __restrict__ w, const float* __restrict__ X,
                            int n, float* __restrict__ out)
{
    const int b = blockIdx.x;
    const int h = blockIdx.y * blockDim.x + threadIdx.x;
    const float* xb = X + (size_t)b * n * HID + h;
    const float* wb = w + b * n;
    float acc = 0.f;
#pragma unroll 4
    for (int r = 0; r < n; r++)
        acc = fmaf(__ldg(&wb[r]), xb[(size_t)r * HID], acc);
    out[b * HID + h] = acc;
}

// ---------------------------------------------------------------------------
// out[0 : B*S*H)        = u[b,:] broadcast over s  (att_dns_features)
// out[B*S*H : 2*B*S*H)  = v[b,:] broadcast over s  (att_img_features)
// ---------------------------------------------------------------------------
__global__ void broadcast_kernel(const float* __restrict__ u, const float* __restrict__ v,
                                 float4* __restrict__ out)
{
    const int i = blockIdx.x * blockDim.x + threadIdx.x;   // float4 index, < 2^22
    const int b  = i >> 17;          // / (SEQ*HID/4) = 131072
    const int h4 = i & 255;          // % (HID/4)
    const float4* u4 = (const float4*)u;
    const float4* v4 = (const float4*)v;
    const float4 uu = u4[b * 256 + h4];
    const float4 vv = v4[b * 256 + h4];
    out[i] = uu;
    out[(BATCH * SEQ * HID / 4) + i] = vv;
}

// ---------------------------------------------------------------------------
extern "C" void kernel_launch(void* const* d_in, const int* in_sizes, int n_in,
                              void* d_out, int out_size)
{
    const float* dns    = (const float*)d_in[0];   // (B,S,H)
    const float* img    = (const float*)d_in[1];   // (B,R,H)
    const float* W_i1   = (const float*)d_in[4];   // (H,H)
    const float* w_att1 = (const float*)d_in[5];   // (2H) -> wB = +H
    const float* W_d2   = (const float*)d_in[7];   // (H,H)
    const float* w_att2 = (const float*)d_in[10];  // (2H) -> wD = +H
    float* out = (float*)d_out;

    float *part1, *part2, *w1, *w2, *v, *u;
    cudaGetSymbolAddress((void**)&part1, g_part1);
    cudaGetSymbolAddress((void**)&part2, g_part2);
    cudaGetSymbolAddress((void**)&w1, g_w1);
    cudaGetSymbolAddress((void**)&w2, g_w2);
    cudaGetSymbolAddress((void**)&v, g_v);
    cudaGetSymbolAddress((void**)&u, g_u);

    // scores (tanh-GEMM-dot), partials per column tile
    gemm_tanh_dot<<<dim3(BATCH * RIMG / BM, NCT), 256>>>(img, W_i1, w_att1 + HID,
                                                         part1, BATCH * RIMG);
    gemm_tanh_dot<<<dim3(BATCH * SEQ / BM, NCT), 256>>>(dns, W_d2, w_att2 + HID,
                                                        part2, BATCH * SEQ);

    // softmax weights per batch
    softmax_rows<<<BATCH, 256>>>(part1, BATCH * RIMG, RIMG, w1);
    softmax_rows<<<BATCH, 256>>>(part2, BATCH * SEQ, SEQ, w2);

    // per-batch attended feature rows
    wsum_kernel<<<dim3(BATCH, HID / 256), 256>>>(w1, img, RIMG, v);
    wsum_kernel<<<dim3(BATCH, HID / 256), 256>>>(w2, dns, SEQ, u);

    // broadcast to full (B,S,H) outputs: att_dns first, att_img second
    broadcast_kernel<<<(BATCH * SEQ * HID / 4) / 256, 256>>>(u, v, (float4*)out);
}

// round 4
// speedup vs baseline: 1.7799x; 1.7799x over previous
#include <cuda_runtime.h>
#include <cuda_bf16.h>
#include <math.h>
#include <stdint.h>

#define HID   1024
#define BATCH 32
#define SEQ   512
#define RIMG  196
#define NCT   8
#define MT    128
#define NT    128
#define KC    32
#define NCHUNK (HID / KC)
#define ROWB  80                      // bytes per smem row (64B data + 16B pad)
#define VERB  (128 * ROWB)            // one matrix version: 10240 B
#define STAGEB (4 * VERB)             // Ahi, Alo, Bhi, Blo
#define WV_OFF (2 * STAGEB)           // 81920
#define RED_OFF (WV_OFF + 512)
#define SMEM_DYN (RED_OFF + 1024)     // 84480-ish

// ---------------- scratch ----------------
__device__ float g_part1[NCT * BATCH * RIMG];
__device__ float g_part2[NCT * BATCH * SEQ];
__device__ float g_w1[BATCH * RIMG];
__device__ float g_w2[BATCH * SEQ];
__device__ float g_v[BATCH * HID];
__device__ float g_u[BATCH * HID];

// ---------------- helpers ----------------
__device__ __forceinline__ uint32_t smem_u32(const void* p) {
    uint32_t a;
    asm("{ .reg .u64 t; cvta.to.shared.u64 t, %1; cvt.u32.u64 %0, t; }" : "=r"(a) : "l"(p));
    return a;
}

__device__ __forceinline__ void ldsm4(uint32_t* r, uint32_t addr) {
    asm volatile("ldmatrix.sync.aligned.m8n8.x4.shared.b16 {%0,%1,%2,%3}, [%4];"
                 : "=r"(r[0]), "=r"(r[1]), "=r"(r[2]), "=r"(r[3]) : "r"(addr));
}

__device__ __forceinline__ void mma16816(float* c, const uint32_t* a,
                                         uint32_t b0, uint32_t b1) {
    asm volatile(
        "mma.sync.aligned.m16n8k16.row.col.f32.bf16.bf16.f32 "
        "{%0,%1,%2,%3}, {%4,%5,%6,%7}, {%8,%9}, {%0,%1,%2,%3};"
        : "+f"(c[0]), "+f"(c[1]), "+f"(c[2]), "+f"(c[3])
        : "r"(a[0]), "r"(a[1]), "r"(a[2]), "r"(a[3]), "r"(b0), "r"(b1));
}

// split two float4 (8 fp32) into 8 bf16 hi (uint4) + 8 bf16 lo (uint4)
__device__ __forceinline__ void split8(float4 va, float4 vb, uint4& hi, uint4& lo) {
    float f[8] = {va.x, va.y, va.z, va.w, vb.x, vb.y, vb.z, vb.w};
    uint32_t h[4], l[4];
#pragma unroll
    for (int i = 0; i < 4; i++) {
        __nv_bfloat16 h0 = __float2bfloat16_rn(f[2 * i]);
        __nv_bfloat16 h1 = __float2bfloat16_rn(f[2 * i + 1]);
        __nv_bfloat16 l0 = __float2bfloat16_rn(f[2 * i] - __bfloat162float(h0));
        __nv_bfloat16 l1 = __float2bfloat16_rn(f[2 * i + 1] - __bfloat162float(h1));
        __nv_bfloat162 hp; hp.x = h0; hp.y = h1;
        __nv_bfloat162 lp; lp.x = l0; lp.y = l1;
        h[i] = *reinterpret_cast<uint32_t*>(&hp);
        l[i] = *reinterpret_cast<uint32_t*>(&lp);
    }
    hi.x = h[0]; hi.y = h[1]; hi.z = h[2]; hi.w = h[3];
    lo.x = l[0]; lo.y = l[1]; lo.z = l[2]; lo.w = l[3];
}

__device__ __forceinline__ float fast_tanh(float x) {
    return 1.f - 2.f / (__expf(2.f * x) + 1.f);
}

// ---------------------------------------------------------------------------
// bf16 split-fp32 mma.sync GEMM(X·Wᵀ) + tanh + dot(wvec) per 128-col tile.
// part[ntile * Ntot + m] = sum over this tile's 128 cols of tanh(C)·wv.
// ---------------------------------------------------------------------------
__global__ __launch_bounds__(256, 1)
void gemm_mma(const float* __restrict__ X, const float* __restrict__ W,
              const float* __restrict__ wvec, float* __restrict__ part, int Ntot)
{
    extern __shared__ char smem[];
    const uint32_t sb = smem_u32(smem);
    const int tid = threadIdx.x, lane = tid & 31, wid = tid >> 5;
    const int ntile = blockIdx.x, mtile = blockIdx.y;

    float* wvsh = (float*)(smem + WV_OFF);
    float* red  = (float*)(smem + RED_OFF);
    if (tid < 128) wvsh[tid] = wvec[ntile * NT + tid];

    const int row  = tid >> 1;
    const int half = tid & 1;
    const float4* Ap = (const float4*)(X + (size_t)(mtile * MT + row) * HID) + half * 4;
    const float4* Bp = (const float4*)(W + (size_t)(ntile * NT + row) * HID) + half * 4;

    const int m_off = (wid & 3) * 32;
    const int n_off = (wid >> 2) * 64;
    const int lm_row  = lane & 15;
    const int lm_colb = (lane & 16) ? 16 : 0;

    float acc[2][8][4];
#pragma unroll
    for (int t = 0; t < 2; t++)
#pragma unroll
        for (int n = 0; n < 8; n++)
#pragma unroll
            for (int j = 0; j < 4; j++) acc[t][n][j] = 0.f;

    float4 va[4], vb[4];
    // prologue: chunk 0
#pragma unroll
    for (int j = 0; j < 4; j++) { va[j] = __ldg(Ap + j); vb[j] = __ldg(Bp + j); }

    const uint32_t st_base = (uint32_t)(row * ROWB + half * 32);
#define STORE_STAGE(sidx)                                                     \
    do {                                                                      \
        char* stp = smem + (sidx) * STAGEB;                                   \
        uint4 h, l;                                                           \
        split8(va[0], va[1], h, l);                                           \
        *(uint4*)(stp + st_base) = h;                                         \
        *(uint4*)(stp + VERB + st_base) = l;                                  \
        split8(va[2], va[3], h, l);                                           \
        *(uint4*)(stp + st_base + 16) = h;                                    \
        *(uint4*)(stp + VERB + st_base + 16) = l;                             \
        split8(vb[0], vb[1], h, l);                                           \
        *(uint4*)(stp + 2 * VERB + st_base) = h;                              \
        *(uint4*)(stp + 3 * VERB + st_base) = l;                              \
        split8(vb[2], vb[3], h, l);                                           \
        *(uint4*)(stp + 2 * VERB + st_base + 16) = h;                         \
        *(uint4*)(stp + 3 * VERB + st_base + 16) = l;                         \
    } while (0)

    STORE_STAGE(0);
    __syncthreads();

    for (int i = 0; i < NCHUNK; ++i) {
        if (i + 1 < NCHUNK) {
#pragma unroll
            for (int j = 0; j < 4; j++) {
                va[j] = __ldg(Ap + (i + 1) * 8 + j);
                vb[j] = __ldg(Bp + (i + 1) * 8 + j);
            }
        }

        // compute chunk i from stage i&1
        const uint32_t SA = sb + (i & 1) * STAGEB;
        const uint32_t SB = SA + 2 * VERB;
#pragma unroll
        for (int ks = 0; ks < 2; ks++) {
            uint32_t ah[2][4], al[2][4];
#pragma unroll
            for (int t = 0; t < 2; t++) {
                uint32_t ad = SA + (uint32_t)((m_off + t * 16 + lm_row) * ROWB + ks * 32 + lm_colb);
                ldsm4(ah[t], ad);
                ldsm4(al[t], ad + VERB);
            }
            uint32_t bh[4][4], bl[4][4];
#pragma unroll
            for (int q = 0; q < 4; q++) {
                uint32_t bd = SB + (uint32_t)((n_off + q * 16 + lm_row) * ROWB + ks * 32 + lm_colb);
                ldsm4(bh[q], bd);
                ldsm4(bl[q], bd + VERB);
            }
#pragma unroll
            for (int t = 0; t < 2; t++)
#pragma unroll
                for (int n8 = 0; n8 < 8; n8++) {
                    const int q = n8 >> 1, u = n8 & 1;
                    mma16816(acc[t][n8], ah[t], bh[q][u], bh[q][u + 2]);
                    mma16816(acc[t][n8], ah[t], bl[q][u], bl[q][u + 2]);
                    mma16816(acc[t][n8], al[t], bh[q][u], bh[q][u + 2]);
                }
        }

        if (i + 1 < NCHUNK) {
            STORE_STAGE((i + 1) & 1);
            __syncthreads();
        }
    }

    // epilogue: tanh + dot(wv), reduce to per-row partials
    float s0[2] = {0.f, 0.f}, s1[2] = {0.f, 0.f};
#pragma unroll
    for (int t = 0; t < 2; t++)
#pragma unroll
        for (int n8 = 0; n8 < 8; n8++) {
            const float w0 = wvsh[n_off + n8 * 8 + (lane & 3) * 2];
            const float w1 = wvsh[n_off + n8 * 8 + (lane & 3) * 2 + 1];
            s0[t] = fmaf(fast_tanh(acc[t][n8][0]), w0, s0[t]);
            s0[t] = fmaf(fast_tanh(acc[t][n8][1]), w1, s0[t]);
            s1[t] = fmaf(fast_tanh(acc[t][n8][2]), w0, s1[t]);
            s1[t] = fmaf(fast_tanh(acc[t][n8][3]), w1, s1[t]);
        }
#pragma unroll
    for (int o = 1; o <= 2; o <<= 1) {
#pragma unroll
        for (int t = 0; t < 2; t++) {
            s0[t] += __shfl_xor_sync(0xffffffffu, s0[t], o);
            s1[t] += __shfl_xor_sync(0xffffffffu, s1[t], o);
        }
    }
    __syncthreads();   // stages no longer needed; red region is separate anyway
    if ((lane & 3) == 0) {
        const int r = lane >> 2;
        float* rw = red + (wid >> 2) * 128;
        rw[m_off + r]      = s0[0];
        rw[m_off + r + 8]  = s1[0];
        rw[m_off + 16 + r]     = s0[1];
        rw[m_off + 16 + r + 8] = s1[1];
    }
    __syncthreads();
    if (tid < 128)
        part[ntile * Ntot + mtile * MT + tid] = red[tid] + red[128 + tid];
}

// ---------------------------------------------------------------------------
__device__ __forceinline__ float warpRedMax(float v) {
#pragma unroll
    for (int o = 16; o > 0; o >>= 1) v = fmaxf(v, __shfl_xor_sync(0xffffffffu, v, o));
    return v;
}
__device__ __forceinline__ float warpRedSum(float v) {
#pragma unroll
    for (int o = 16; o > 0; o >>= 1) v += __shfl_xor_sync(0xffffffffu, v, o);
    return v;
}

__global__ void softmax_rows(const float* __restrict__ part, int N, int n,
                             float* __restrict__ w)
{
    __shared__ float sh[8];
    const int b = blockIdx.x, tid = threadIdx.x, base = b * n;

    float m = -1e30f;
    for (int i = tid; i < n; i += 256) {
        float x = 0.f;
#pragma unroll
        for (int c = 0; c < NCT; c++) x += part[c * N + base + i];
        w[base + i] = x;
        m = fmaxf(m, x);
    }
    m = warpRedMax(m);
    if ((tid & 31) == 0) sh[tid >> 5] = m;
    __syncthreads();
    float M = sh[0];
#pragma unroll
    for (int t = 1; t < 8; t++) M = fmaxf(M, sh[t]);

    float sum = 0.f;
    for (int i = tid; i < n; i += 256) {
        float e = expf(w[base + i] - M);
        w[base + i] = e;
        sum += e;
    }
    sum = warpRedSum(sum);
    __syncthreads();
    if ((tid & 31) == 0) sh[tid >> 5] = sum;
    __syncthreads();
    float S = 0.f;
#pragma unroll
    for (int t = 0; t < 8; t++) S += sh[t];
    const float inv = 1.f / S;
    for (int i = tid; i < n; i += 256) w[base + i] *= inv;
}

__global__ void wsum_kernel(const float* __restrict__ w, const float* __restrict__ X,
                            int n, float* __restrict__ out)
{
    const int b = blockIdx.x;
    const int h = blockIdx.y * blockDim.x + threadIdx.x;
    const float* xb = X + (size_t)b * n * HID + h;
    const float* wb = w + b * n;
    float acc = 0.f;
#pragma unroll 4
    for (int r = 0; r < n; r++)
        acc = fmaf(__ldg(&wb[r]), xb[(size_t)r * HID], acc);
    out[b * HID + h] = acc;
}

__global__ void broadcast_kernel(const float* __restrict__ u, const float* __restrict__ v,
                                 float4* __restrict__ out)
{
    const int i  = blockIdx.x * blockDim.x + threadIdx.x;
    const int b  = i >> 17;
    const int h4 = i & 255;
    const float4* u4 = (const float4*)u;
    const float4* v4 = (const float4*)v;
    out[i] = u4[b * 256 + h4];
    out[(BATCH * SEQ * HID / 4) + i] = v4[b * 256 + h4];
}

// ---------------------------------------------------------------------------
extern "C" void kernel_launch(void* const* d_in, const int* in_sizes, int n_in,
                              void* d_out, int out_size)
{
    const float* dns    = (const float*)d_in[0];
    const float* img    = (const float*)d_in[1];
    const float* W_i1   = (const float*)d_in[4];
    const float* w_att1 = (const float*)d_in[5];
    const float* W_d2   = (const float*)d_in[7];
    const float* w_att2 = (const float*)d_in[10];
    float* out = (float*)d_out;

    float *part1, *part2, *w1, *w2, *v, *u;
    cudaGetSymbolAddress((void**)&part1, g_part1);
    cudaGetSymbolAddress((void**)&part2, g_part2);
    cudaGetSymbolAddress((void**)&w1, g_w1);
    cudaGetSymbolAddress((void**)&w2, g_w2);
    cudaGetSymbolAddress((void**)&v, g_v);
    cudaGetSymbolAddress((void**)&u, g_u);

    cudaFuncSetAttribute(gemm_mma, cudaFuncAttributeMaxDynamicSharedMemorySize, SMEM_DYN);

    gemm_mma<<<dim3(NCT, BATCH * RIMG / MT), 256, SMEM_DYN>>>(img, W_i1, w_att1 + HID,
                                                              part1, BATCH * RIMG);
    gemm_mma<<<dim3(NCT, BATCH * SEQ / MT), 256, SMEM_DYN>>>(dns, W_d2, w_att2 + HID,
                                                             part2, BATCH * SEQ);

    softmax_rows<<<BATCH, 256>>>(part1, BATCH * RIMG, RIMG, w1);
    softmax_rows<<<BATCH, 256>>>(part2, BATCH * SEQ, SEQ, w2);

    wsum_kernel<<<dim3(BATCH, HID / 256), 256>>>(w1, img, RIMG, v);
    wsum_kernel<<<dim3(BATCH, HID / 256), 256>>>(w2, dns, SEQ, u);

    broadcast_kernel<<<(BATCH * SEQ * HID / 4) / 256, 256>>>(u, v, (float4*)out);
}